// round 1
// baseline (speedup 1.0000x reference)
#include <cuda_runtime.h>

// ----------------------------------------------------------------------------
// RBF kernel: K[i,j] = exp(-inv * (||x_i||^2 - 2 x_i.y_j + ||y_j||^2))
// N = M = 8192, D = 128, fp32.
// Strategy: fp32 SGEMM (CUDA cores, packed fma.rn.f32x2) + exp epilogue.
// ----------------------------------------------------------------------------

#define BM 128
#define BN 128
#define BK 16
#define PITCH 132   // 128 + 4 floats, keeps rows 16B-aligned

__device__ float g_x2[8192];
__device__ float g_y2[8192];

// ---- packed f32x2 helpers (FFMA2 path: 2x fp32 FMA rate on sm_103a) --------
__device__ __forceinline__ void ffma2(unsigned long long& c,
                                      unsigned long long a,
                                      unsigned long long b) {
    asm("fma.rn.f32x2 %0, %1, %2, %0;" : "+l"(c) : "l"(a), "l"(b));
}
__device__ __forceinline__ unsigned long long dupf(float a) {
    unsigned long long r;
    asm("mov.b64 %0, {%1, %1};" : "=l"(r) : "f"(a));
    return r;
}
__device__ __forceinline__ unsigned long long packf(float lo, float hi) {
    unsigned long long r;
    asm("mov.b64 %0, {%1, %2};" : "=l"(r) : "f"(lo), "f"(hi));
    return r;
}
__device__ __forceinline__ float2 unpk(unsigned long long v) {
    float2 f;
    asm("mov.b64 {%0, %1}, %2;" : "=f"(f.x), "=f"(f.y) : "l"(v));
    return f;
}

// ---- row-norm precompute: one warp per row ---------------------------------
__global__ void norms_kernel(const float* __restrict__ X,
                             const float* __restrict__ Y,
                             int nX, int nY) {
    int warp = (blockIdx.x * blockDim.x + threadIdx.x) >> 5;
    int lane = threadIdx.x & 31;
    if (warp >= nX + nY) return;
    const float* src;
    float* dst;
    int row;
    if (warp < nX) { src = X; dst = g_x2; row = warp; }
    else           { src = Y; dst = g_y2; row = warp - nX; }
    float4 v = ((const float4*)(src + (size_t)row * 128))[lane];
    float s = v.x * v.x + v.y * v.y + v.z * v.z + v.w * v.w;
    #pragma unroll
    for (int o = 16; o > 0; o >>= 1) s += __shfl_xor_sync(0xffffffffu, s, o);
    if (lane == 0) dst[row] = s;
}

// ---- main GEMM + exp kernel ------------------------------------------------
__global__ __launch_bounds__(256, 2)
void rbf_kernel(const float* __restrict__ X,
                const float* __restrict__ Y,
                const float* __restrict__ sigma,
                float* __restrict__ out,
                int Mtot) {
    __shared__ float As[2][BK][PITCH];  // transposed: [k][m]
    __shared__ float Bs[2][BK][PITCH];  // transposed: [k][n]

    const int tid = threadIdx.x;
    const int tx = tid & 15;        // 0..15  -> 8 cols each
    const int ty = tid >> 4;        // 0..15  -> 8 rows each
    const int row0 = blockIdx.y * BM;
    const int col0 = blockIdx.x * BN;

    // global-load mapping: lm0 = row-within-tile (pass 0), lk4 = float4 within chunk
    const int lm0 = tid >> 2;       // 0..63
    const int lk4 = tid & 3;        // 0..3   (4 float4 = 16 floats = BK)

    const float* Xp = X + (size_t)(row0 + lm0) * 128 + lk4 * 4;
    const float* Yp = Y + (size_t)(col0 + lm0) * 128 + lk4 * 4;

    unsigned long long acc[8][4];
    #pragma unroll
    for (int i = 0; i < 8; i++)
        #pragma unroll
        for (int j = 0; j < 4; j++) acc[i][j] = 0ull;

    // prefetch chunk 0
    float4 ra0 = *(const float4*)(Xp);
    float4 ra1 = *(const float4*)(Xp + 64 * 128);
    float4 rb0 = *(const float4*)(Yp);
    float4 rb1 = *(const float4*)(Yp + 64 * 128);

    {
        const float* pa0 = (const float*)&ra0;
        const float* pa1 = (const float*)&ra1;
        const float* pb0 = (const float*)&rb0;
        const float* pb1 = (const float*)&rb1;
        #pragma unroll
        for (int i = 0; i < 4; i++) {
            As[0][4 * lk4 + i][lm0]      = pa0[i];
            As[0][4 * lk4 + i][lm0 + 64] = pa1[i];
            Bs[0][4 * lk4 + i][lm0]      = pb0[i];
            Bs[0][4 * lk4 + i][lm0 + 64] = pb1[i];
        }
    }
    __syncthreads();

    #pragma unroll 1
    for (int c = 0; c < 8; ++c) {
        const int cur = c & 1;
        if (c < 7) {
            int off = (c + 1) * BK;
            ra0 = *(const float4*)(Xp + off);
            ra1 = *(const float4*)(Xp + 64 * 128 + off);
            rb0 = *(const float4*)(Yp + off);
            rb1 = *(const float4*)(Yp + 64 * 128 + off);
        }

        #pragma unroll
        for (int k = 0; k < BK; k++) {
            float4 a0 = *(const float4*)&As[cur][k][ty * 8];
            float4 a1 = *(const float4*)&As[cur][k][ty * 8 + 4];
            float4 b0 = *(const float4*)&Bs[cur][k][tx * 8];
            float4 b1 = *(const float4*)&Bs[cur][k][tx * 8 + 4];
            unsigned long long bp0 = packf(b0.x, b0.y);
            unsigned long long bp1 = packf(b0.z, b0.w);
            unsigned long long bp2 = packf(b1.x, b1.y);
            unsigned long long bp3 = packf(b1.z, b1.w);
            float av[8] = {a0.x, a0.y, a0.z, a0.w, a1.x, a1.y, a1.z, a1.w};
            #pragma unroll
            for (int i = 0; i < 8; i++) {
                unsigned long long ad = dupf(av[i]);
                ffma2(acc[i][0], ad, bp0);
                ffma2(acc[i][1], ad, bp1);
                ffma2(acc[i][2], ad, bp2);
                ffma2(acc[i][3], ad, bp3);
            }
        }

        if (c < 7) {
            const int nxt = cur ^ 1;
            const float* pa0 = (const float*)&ra0;
            const float* pa1 = (const float*)&ra1;
            const float* pb0 = (const float*)&rb0;
            const float* pb1 = (const float*)&rb1;
            #pragma unroll
            for (int i = 0; i < 4; i++) {
                As[nxt][4 * lk4 + i][lm0]      = pa0[i];
                As[nxt][4 * lk4 + i][lm0 + 64] = pa1[i];
                Bs[nxt][4 * lk4 + i][lm0]      = pb0[i];
                Bs[nxt][4 * lk4 + i][lm0 + 64] = pb1[i];
            }
        }
        __syncthreads();
    }

    // ---- epilogue: dnorm2 -> exp -> store ----------------------------------
    float s = sigma[0];
    float inv = 1.0f / (s * s + 1e-9f);
    const int grow = row0 + ty * 8;
    const int gcol = col0 + tx * 8;

    float y2v[8];
    #pragma unroll
    for (int j = 0; j < 8; j++) y2v[j] = g_y2[gcol + j];

    #pragma unroll
    for (int i = 0; i < 8; i++) {
        float x2 = g_x2[grow + i];
        float2 d0 = unpk(acc[i][0]);
        float2 d1 = unpk(acc[i][1]);
        float2 d2 = unpk(acc[i][2]);
        float2 d3 = unpk(acc[i][3]);
        float4 o0, o1;
        o0.x = expf(-inv * (x2 - 2.0f * d0.x + y2v[0]));
        o0.y = expf(-inv * (x2 - 2.0f * d0.y + y2v[1]));
        o0.z = expf(-inv * (x2 - 2.0f * d1.x + y2v[2]));
        o0.w = expf(-inv * (x2 - 2.0f * d1.y + y2v[3]));
        o1.x = expf(-inv * (x2 - 2.0f * d2.x + y2v[4]));
        o1.y = expf(-inv * (x2 - 2.0f * d2.y + y2v[5]));
        o1.z = expf(-inv * (x2 - 2.0f * d3.x + y2v[6]));
        o1.w = expf(-inv * (x2 - 2.0f * d3.y + y2v[7]));
        size_t base = (size_t)(grow + i) * (size_t)Mtot + gcol;
        *(float4*)&out[base]     = o0;
        *(float4*)&out[base + 4] = o1;
    }
}

// ----------------------------------------------------------------------------
extern "C" void kernel_launch(void* const* d_in, const int* in_sizes, int n_in,
                              void* d_out, int out_size) {
    const float* X = (const float*)d_in[0];
    const float* Y = (const float*)d_in[1];
    const float* sigma = (const float*)d_in[2];
    float* out = (float*)d_out;

    const int D = 128;
    const int n = in_sizes[0] / D;   // 8192
    const int m = in_sizes[1] / D;   // 8192

    // row norms: one warp per row, X rows then Y rows
    {
        int warps = n + m;
        int threads = 256;
        int blocks = (warps * 32 + threads - 1) / threads;
        norms_kernel<<<blocks, threads>>>(X, Y, n, m);
    }

    // main GEMM + exp
    {
        dim3 grid(m / BN, n / BM);
        rbf_kernel<<<grid, 256>>>(X, Y, sigma, out, m);
    }
}